// round 1
// baseline (speedup 1.0000x reference)
#include <cuda_runtime.h>
#include <math.h>

#define NMAX 20000
#define EMAX 320000
#define TEMAX (EMAX + NMAX)
#define BMAXG 64
#define S2S_CAP 4096

// ---------------- static device scratch (no allocations allowed) ----------------
__device__ __align__(16) float g_h[NMAX * 256];     // GEMM output (pre-attention features)
__device__ __align__(16) float g_feat[NMAX * 256];  // layer output / next layer input
__device__ float g_s[NMAX * 4];
__device__ float g_d[NMAX * 4];
__device__ int g_rowptr[NMAX + 1];
__device__ int g_wptr[NMAX];       // doubles as counts, then write cursors
__device__ int g_col[TEMAX];
__device__ int g_gcnt[BMAXG];
__device__ int g_gptr[BMAXG + 1];
__device__ float g_qstar[BMAXG * 256];
__device__ float g_hs[BMAXG * 128];
__device__ float g_cs[BMAXG * 128];
__device__ float g_gf[BMAXG * 32];

// ---------------- init ----------------
__global__ void k_init(int n) {
    int i = blockIdx.x * blockDim.x + threadIdx.x;
    if (i < n) g_wptr[i] = 0;
    if (i < BMAXG) g_gcnt[i] = 0;
    if (i < BMAXG * 256) g_qstar[i] = 0.f;
    if (i < BMAXG * 128) { g_hs[i] = 0.f; g_cs[i] = 0.f; }
}

// ---------------- CSR build ----------------
__global__ void k_edge_hist(const int* __restrict__ ei, int E, int n) {
    int i = blockIdx.x * blockDim.x + threadIdx.x;
    int TE = E + n;
    if (i >= TE) return;
    int dv = (i < E) ? ei[E + i] : (i - E);
    atomicAdd(&g_wptr[dv], 1);
}

__global__ void k_batch_hist(const int* __restrict__ batch, int n) {
    int i = blockIdx.x * blockDim.x + threadIdx.x;
    if (i < n) atomicAdd(&g_gcnt[batch[i]], 1);
}

// single-block exclusive scan; optionally mirrors offsets into wcopy
__global__ void k_scan(const int* __restrict__ cnt, int n, int* __restrict__ outp,
                       int* __restrict__ wcopy) {
    __shared__ int part[1024];
    int tid = threadIdx.x;
    int chunk = (n + 1023) >> 10;
    int s0 = tid * chunk;
    int s1 = s0 + chunk; if (s1 > n) s1 = n;
    int s = 0;
    for (int i = s0; i < s1; i++) s += cnt[i];
    part[tid] = s;
    __syncthreads();
    for (int off = 1; off < 1024; off <<= 1) {
        int v = (tid >= off) ? part[tid - off] : 0;
        __syncthreads();
        part[tid] += v;
        __syncthreads();
    }
    int run = (tid > 0) ? part[tid - 1] : 0;
    for (int i = s0; i < s1; i++) {
        int c = cnt[i];          // read before any aliasing write
        outp[i] = run;
        if (wcopy) wcopy[i] = run;
        run += c;
    }
    if (tid == 1023) outp[n] = part[1023];
}

__global__ void k_edge_scatter(const int* __restrict__ ei, int E, int n) {
    int i = blockIdx.x * blockDim.x + threadIdx.x;
    int TE = E + n;
    if (i >= TE) return;
    int sv, dv;
    if (i < E) { sv = ei[i]; dv = ei[E + i]; } else { sv = dv = i - E; }
    int pos = atomicAdd(&g_wptr[dv], 1);
    g_col[pos] = sv;
}

// ---------------- GEMM: Out[n,M] = A[n,K] @ W[K,M], fp32, 128x64 tile ----------------
__global__ __launch_bounds__(256) void k_gemm(const float* __restrict__ A,
                                              const float* __restrict__ W,
                                              float* __restrict__ Out,
                                              int n, int K, int M) {
    __shared__ float As[16][128];
    __shared__ float Bs[16][64];
    int tid = threadIdx.x;
    int tx = tid & 15, ty = tid >> 4;
    int rb = blockIdx.x * 128;
    int cb = blockIdx.y * 64;

    float acc[8][4];
#pragma unroll
    for (int i = 0; i < 8; i++)
#pragma unroll
        for (int j = 0; j < 4; j++) acc[i][j] = 0.f;

    for (int k0 = 0; k0 < K; k0 += 16) {
#pragma unroll
        for (int t = 0; t < 2; t++) {
            int idx = tid + t * 256;          // 512 float4 loads for A tile
            int r = idx >> 2;                 // 0..127
            int kc = (idx & 3) << 2;          // 0,4,8,12
            int gr = rb + r; if (gr >= n) gr = n - 1;
            float4 v = *(const float4*)(A + (size_t)gr * K + k0 + kc);
            As[kc + 0][r] = v.x; As[kc + 1][r] = v.y;
            As[kc + 2][r] = v.z; As[kc + 3][r] = v.w;
        }
        {
            int r = tid >> 4;                 // 0..15
            int c = (tid & 15) << 2;          // 0..60
            float4 v = *(const float4*)(W + (size_t)(k0 + r) * M + cb + c);
            *(float4*)&Bs[r][c] = v;
        }
        __syncthreads();
#pragma unroll
        for (int kk = 0; kk < 16; kk++) {
            float4 a0 = *(float4*)&As[kk][ty * 8];
            float4 a1 = *(float4*)&As[kk][ty * 8 + 4];
            float4 b0 = *(float4*)&Bs[kk][tx * 4];
            float av[8] = {a0.x, a0.y, a0.z, a0.w, a1.x, a1.y, a1.z, a1.w};
            float bv[4] = {b0.x, b0.y, b0.z, b0.w};
#pragma unroll
            for (int i = 0; i < 8; i++)
#pragma unroll
                for (int j = 0; j < 4; j++) acc[i][j] = fmaf(av[i], bv[j], acc[i][j]);
        }
        __syncthreads();
    }
#pragma unroll
    for (int i = 0; i < 8; i++) {
        int gr = rb + ty * 8 + i;
        if (gr < n) {
            float4 o = make_float4(acc[i][0], acc[i][1], acc[i][2], acc[i][3]);
            *(float4*)(Out + (size_t)gr * M + cb + tx * 4) = o;
        }
    }
}

// ---------------- per-(node,head) attention logits: warp per row ----------------
template <int H, int C>
__global__ void k_sd(const float* __restrict__ h, const float* __restrict__ asrc,
                     const float* __restrict__ adst, int n) {
    int w = (blockIdx.x * blockDim.x + threadIdx.x) >> 5;
    int lane = threadIdx.x & 31;
    if (w >= n * H) return;
    int hh = w % H;
    const float* hp = h + (size_t)w * C;
    float ss = 0.f, dd = 0.f;
    for (int c = lane; c < C; c += 32) {
        float hv = hp[c];
        ss = fmaf(hv, asrc[hh * C + c], ss);
        dd = fmaf(hv, adst[hh * C + c], dd);
    }
#pragma unroll
    for (int off = 16; off > 0; off >>= 1) {
        ss += __shfl_xor_sync(0xffffffffu, ss, off);
        dd += __shfl_xor_sync(0xffffffffu, dd, off);
    }
    if (lane == 0) { g_s[w] = ss; g_d[w] = dd; }
}

// ---------------- GAT attention + scatter + bias + ELU: warp per dst node ----------------
template <int H, int C>
__global__ void k_attn(const float* __restrict__ h, const float* __restrict__ bias,
                       float* __restrict__ out, int n) {
    int v = (blockIdx.x * blockDim.x + threadIdx.x) >> 5;
    int lane = threadIdx.x & 31;
    if (v >= n) return;
    int beg = g_rowptr[v], end = g_rowptr[v + 1];

    float dv[H];
#pragma unroll
    for (int t = 0; t < H; t++) dv[t] = g_d[v * H + t];

    // pass 1: per-head max over incoming edges
    float m[H];
#pragma unroll
    for (int t = 0; t < H; t++) m[t] = -1e30f;
    for (int j = beg + lane; j < end; j += 32) {
        int u = g_col[j];
#pragma unroll
        for (int t = 0; t < H; t++) {
            float e = g_s[u * H + t] + dv[t];
            e = (e > 0.f) ? e : 0.2f * e;
            m[t] = fmaxf(m[t], e);
        }
    }
#pragma unroll
    for (int t = 0; t < H; t++)
#pragma unroll
        for (int off = 16; off > 0; off >>= 1)
            m[t] = fmaxf(m[t], __shfl_xor_sync(0xffffffffu, m[t], off));

    // pass 2: serial edges, channel-parallel lanes
    constexpr int F = H * C / 32;   // 8 (layers 1/2), 4 (layer 3)
    int hh = (lane * F) / C;
    float mh = m[hh];
    float dvh = dv[hh];
    float acc[F];
#pragma unroll
    for (int q = 0; q < F; q++) acc[q] = 0.f;
    float den = 0.f;

    for (int j = beg; j < end; j++) {
        int u = g_col[j];
        float e = g_s[u * H + hh] + dvh;
        e = (e > 0.f) ? e : 0.2f * e;
        float ex = __expf(e - mh);
        den += ex;
        const float4* hp = (const float4*)(h + (size_t)u * (H * C)) + lane * (F / 4);
#pragma unroll
        for (int q = 0; q < F / 4; q++) {
            float4 hv = hp[q];
            acc[q * 4 + 0] = fmaf(ex, hv.x, acc[q * 4 + 0]);
            acc[q * 4 + 1] = fmaf(ex, hv.y, acc[q * 4 + 1]);
            acc[q * 4 + 2] = fmaf(ex, hv.z, acc[q * 4 + 2]);
            acc[q * 4 + 3] = fmaf(ex, hv.w, acc[q * 4 + 3]);
        }
    }
    float inv = 1.f / (den + 1e-16f);
#pragma unroll
    for (int q = 0; q < F; q++) {
        int c = lane * F + q;
        float o = acc[q] * inv + bias[c];
        o = (o > 0.f) ? o : expm1f(o);
        out[(size_t)v * (H * C) + c] = o;
    }
}

// ---------------- Set2Set LSTM step: one block per graph ----------------
__global__ void k_lstm(const float* __restrict__ Wih, const float* __restrict__ Whh,
                       const float* __restrict__ bih, const float* __restrict__ bhh) {
    int b = blockIdx.x;
    int j = threadIdx.x;  // 128
    __shared__ float q[256], hp[128];
    q[j] = g_qstar[b * 256 + j];
    q[j + 128] = g_qstar[b * 256 + 128 + j];
    hp[j] = g_hs[b * 128 + j];
    __syncthreads();
    float g4[4];
#pragma unroll
    for (int gi = 0; gi < 4; gi++) {
        int row = gi * 128 + j;
        float a = bih[row] + bhh[row];
        const float* wi = Wih + (size_t)row * 256;
        const float* wh = Whh + (size_t)row * 128;
        for (int k = 0; k < 256; k++) a = fmaf(q[k], wi[k], a);
        for (int k = 0; k < 128; k++) a = fmaf(hp[k], wh[k], a);
        g4[gi] = a;
    }
    float ig = 1.f / (1.f + __expf(-g4[0]));
    float fg = 1.f / (1.f + __expf(-g4[1]));
    float gg = tanhf(g4[2]);
    float og = 1.f / (1.f + __expf(-g4[3]));
    float c = fg * g_cs[b * 128 + j] + ig * gg;
    float hh = og * tanhf(c);
    g_cs[b * 128 + j] = c;
    g_hs[b * 128 + j] = hh;
}

// ---------------- Set2Set attention pool: one block per graph ----------------
__global__ void k_pool(const float* __restrict__ x) {
    int g = blockIdx.x;
    int tid = threadIdx.x;  // 128
    __shared__ float q[128];
    __shared__ float e_sh[S2S_CAP];
    __shared__ float red[128];
    __shared__ float sval;
    int beg = g_gptr[g], end = g_gptr[g + 1];
    int cnt = end - beg;
    q[tid] = g_hs[g * 128 + tid];
    __syncthreads();

    float lmax = -1e30f;
    for (int i = tid; i < cnt; i += 128) {
        const float* xp = x + (size_t)(beg + i) * 128;
        float e = 0.f;
        for (int k = 0; k < 128; k++) e = fmaf(xp[k], q[k], e);
        if (i < S2S_CAP) e_sh[i] = e;
        lmax = fmaxf(lmax, e);
    }
    red[tid] = lmax;
    __syncthreads();
    for (int s = 64; s > 0; s >>= 1) {
        if (tid < s) red[tid] = fmaxf(red[tid], red[tid + s]);
        __syncthreads();
    }
    if (tid == 0) sval = red[0];
    __syncthreads();
    float emax = sval;
    __syncthreads();

    float lsum = 0.f;
    for (int i = tid; i < cnt; i += 128) {
        float e;
        if (i < S2S_CAP) e = e_sh[i];
        else {
            const float* xp = x + (size_t)(beg + i) * 128;
            e = 0.f;
            for (int k = 0; k < 128; k++) e = fmaf(xp[k], q[k], e);
        }
        float a = __expf(e - emax);
        if (i < S2S_CAP) e_sh[i] = a;
        lsum += a;
    }
    red[tid] = lsum;
    __syncthreads();
    for (int s = 64; s > 0; s >>= 1) {
        if (tid < s) red[tid] += red[tid + s];
        __syncthreads();
    }
    if (tid == 0) sval = red[0];
    __syncthreads();
    float inv = 1.f / (sval + 1e-16f);

    // r: thread = channel
    float r = 0.f;
    for (int i = 0; i < cnt; i++) {
        float a;
        if (i < S2S_CAP) a = e_sh[i];
        else {
            const float* xp = x + (size_t)(beg + i) * 128;
            float e = 0.f;
            for (int k = 0; k < 128; k++) e = fmaf(xp[k], q[k], e);
            a = __expf(e - emax);
        }
        r = fmaf(a, x[(size_t)(beg + i) * 128 + tid], r);
    }
    g_qstar[g * 256 + tid] = q[tid];
    g_qstar[g * 256 + 128 + tid] = r * inv;
}

// ---------------- graph-feature MLP ----------------
__global__ void k_gf(const float* __restrict__ gfeat, const float* __restrict__ gW1,
                     const float* __restrict__ gb1, const float* __restrict__ gW2,
                     const float* __restrict__ gb2) {
    int b = blockIdx.x;
    int j = threadIdx.x;  // 64
    __shared__ float hid[64];
    float a = gb1[j];
    for (int k = 0; k < 9; k++) a = fmaf(gfeat[b * 9 + k], gW1[k * 64 + j], a);
    hid[j] = fmaxf(a, 0.f);
    __syncthreads();
    if (j < 32) {
        float o = gb2[j];
        for (int k = 0; k < 64; k++) o = fmaf(hid[k], gW2[k * 32 + j], o);
        g_gf[b * 32 + j] = o;
    }
}

// ---------------- final scorer MLP ----------------
__global__ void k_final(const float* __restrict__ mW1, const float* __restrict__ mb1,
                        const float* __restrict__ mW2, const float* __restrict__ mb2,
                        float* __restrict__ out) {
    int b = blockIdx.x;
    int j = threadIdx.x;  // 128
    __shared__ float z[288];
    __shared__ float hid[128];
    z[j] = g_qstar[b * 256 + j];
    z[j + 128] = g_qstar[b * 256 + 128 + j];
    if (j < 32) z[256 + j] = g_gf[b * 32 + j];
    __syncthreads();
    float a = mb1[j];
    for (int k = 0; k < 288; k++) a = fmaf(z[k], mW1[k * 128 + j], a);
    hid[j] = fmaxf(a, 0.f);
    __syncthreads();
    if (j < 4) {
        float o = mb2[j];
        for (int k = 0; k < 128; k++) o = fmaf(hid[k], mW2[k * 4 + j], o);
        out[b * 4 + j] = o;
    }
}

// ---------------- launch ----------------
extern "C" void kernel_launch(void* const* d_in, const int* in_sizes, int n_in,
                              void* d_out, int out_size) {
    const float* x      = (const float*)d_in[0];
    const int*   ei     = (const int*)d_in[1];
    const int*   batch  = (const int*)d_in[2];
    const float* gfeat  = (const float*)d_in[3];
    const float* W1     = (const float*)d_in[4];
    const float* a_src1 = (const float*)d_in[5];
    const float* a_dst1 = (const float*)d_in[6];
    const float* b1     = (const float*)d_in[7];
    const float* W2     = (const float*)d_in[8];
    const float* a_src2 = (const float*)d_in[9];
    const float* a_dst2 = (const float*)d_in[10];
    const float* b2     = (const float*)d_in[11];
    const float* W3     = (const float*)d_in[12];
    const float* a_src3 = (const float*)d_in[13];
    const float* a_dst3 = (const float*)d_in[14];
    const float* b3     = (const float*)d_in[15];
    const float* Wih    = (const float*)d_in[16];
    const float* Whh    = (const float*)d_in[17];
    const float* bih    = (const float*)d_in[18];
    const float* bhh    = (const float*)d_in[19];
    const float* gW1    = (const float*)d_in[20];
    const float* gb1    = (const float*)d_in[21];
    const float* gW2    = (const float*)d_in[22];
    const float* gb2    = (const float*)d_in[23];
    const float* mW1    = (const float*)d_in[24];
    const float* mb1    = (const float*)d_in[25];
    const float* mW2    = (const float*)d_in[26];
    const float* mb2    = (const float*)d_in[27];

    int n  = in_sizes[0] / 128;
    int E  = in_sizes[1] / 2;
    int nb = in_sizes[3] / 9;
    int TE = E + n;

    float *ph, *pfeat;
    int *p_wptr, *p_rowptr, *p_gcnt, *p_gptr;
    cudaGetSymbolAddress((void**)&ph, g_h);
    cudaGetSymbolAddress((void**)&pfeat, g_feat);
    cudaGetSymbolAddress((void**)&p_wptr, g_wptr);
    cudaGetSymbolAddress((void**)&p_rowptr, g_rowptr);
    cudaGetSymbolAddress((void**)&p_gcnt, g_gcnt);
    cudaGetSymbolAddress((void**)&p_gptr, g_gptr);

    // init + CSR build (graph topology is the same across all layers)
    k_init<<<(n + 255) / 256, 256>>>(n);
    k_edge_hist<<<(TE + 255) / 256, 256>>>(ei, E, n);
    k_batch_hist<<<(n + 255) / 256, 256>>>(batch, n);
    k_scan<<<1, 1024>>>(p_wptr, n, p_rowptr, p_wptr);
    k_scan<<<1, 1024>>>(p_gcnt, nb, p_gptr, (int*)nullptr);
    k_edge_scatter<<<(TE + 255) / 256, 256>>>(ei, E, n);

    dim3 gg256((n + 127) / 128, 4);  // M=256
    dim3 gg128((n + 127) / 128, 2);  // M=128
    int sd_blocks4 = (n * 4 * 32 + 255) / 256;
    int sd_blocks1 = (n * 1 * 32 + 255) / 256;
    int attn_blocks = (n * 32 + 255) / 256;

    // layer 1: 128 -> 4x64
    k_gemm<<<gg256, 256>>>(x, W1, ph, n, 128, 256);
    k_sd<4, 64><<<sd_blocks4, 256>>>(ph, a_src1, a_dst1, n);
    k_attn<4, 64><<<attn_blocks, 256>>>(ph, b1, pfeat, n);

    // layer 2: 256 -> 4x64
    k_gemm<<<gg256, 256>>>(pfeat, W2, ph, n, 256, 256);
    k_sd<4, 64><<<sd_blocks4, 256>>>(ph, a_src2, a_dst2, n);
    k_attn<4, 64><<<attn_blocks, 256>>>(ph, b2, pfeat, n);

    // layer 3: 256 -> 1x128
    k_gemm<<<gg128, 256>>>(pfeat, W3, ph, n, 256, 128);
    k_sd<1, 128><<<sd_blocks1, 256>>>(ph, a_src3, a_dst3, n);
    k_attn<1, 128><<<attn_blocks, 256>>>(ph, b3, pfeat, n);

    // Set2Set (3 steps)
    for (int step = 0; step < 3; step++) {
        k_lstm<<<nb, 128>>>(Wih, Whh, bih, bhh);
        k_pool<<<nb, 128>>>(pfeat);
    }

    // heads
    k_gf<<<nb, 64>>>(gfeat, gW1, gb1, gW2, gb2);
    k_final<<<nb, 128>>>(mW1, mb1, mW2, mb2, (float*)d_out);
}